// round 10
// baseline (speedup 1.0000x reference)
#include <cuda_runtime.h>
#include <math.h>
#include <stdint.h>

// Problem constants (B=8, L=4096, D=1024, fp32)
#define BB 8
#define LL 4096
#define ND (LL - 1)        // 4095 deltas per batch
#define NI (LL - 2)        // 4094 loss terms per batch
#define TC 111             // terms per block
#define NDEL (TC + 1)      // 112 deltas per block (rows t0 .. t0+112)
#define NROWS (NDEL + 1)   // 113 rows per block
#define XBLK 37            // 37*111 = 4107 >= 4094
// grid = (37, 8) = 296 = 148 SMs * 2 CTAs -> ONE perfectly balanced wave

#define RING 16            // cp.async row ring depth (16 rows x 4KB = 64 KB)

// Dynamic smem layout (bytes):
//   [0, 65536)            ring: RING rows x 256 float4
//   [65536, 94208)        s_part[NDEL][64]
//   [94208, 94656)        delta_sm[NDEL]
#define SM_RING    0
#define SM_SPART   65536
#define SM_DELTA   (65536 + NDEL * 64 * 4)
#define SM_TOTAL   (SM_DELTA + NDEL * 4)

// Accumulators. Zero-initialized at load; last block resets them each launch.
__device__ float g_ws;
__device__ float g_ms;
__device__ unsigned int g_ticket;

__device__ __forceinline__ float sqnorm_diff(float4 a, float4 b) {
    float dx = a.x - b.x, dy = a.y - b.y, dz = a.z - b.z, dw = a.w - b.w;
    return fmaf(dx, dx, fmaf(dy, dy, fmaf(dz, dz, dw * dw)));
}

__device__ __forceinline__ void cp_async16(uint32_t smem_dst, const float4* gsrc) {
    asm volatile("cp.async.cg.shared.global [%0], [%1], 16;"
                 :: "r"(smem_dst), "l"(gsrc));
}
__device__ __forceinline__ void cp_commit() {
    asm volatile("cp.async.commit_group;");
}
template <int N>
__device__ __forceinline__ void cp_wait() {
    asm volatile("cp.async.wait_group %0;" :: "n"(N));
}

// Fused kernel. Block (bx, b) owns terms t in [111*bx, 111*bx+111) ∩ [0, NI).
// Phase 1: DECOUPLED stream — cp.async (LDGSTS, no dest-register scoreboard)
//          prefetches rows into a 16-row smem ring; each thread consumes only
//          its own 16 B (wait_group is sufficient, no barriers in the loop).
//          prev row carried in a register. Per delta: 1 LDS.128 + 4 FMA +
//          2 SHFL (xor16, xor8); lanes 0..7 store into s_part[i][warp*8+lane].
// Phase 2: warp w reduces deltas i ≡ w (mod 8): 2 LDS + 5 SHFL + sqrt.
// Phase 3: warp 0 computes 111 weighted loss terms (4 per lane), one
//          atomicAdd pair per block; ticketed last block publishes + resets.
//
// Row addresses are clamped to L-1: out-of-range deltas become 0 and their
// terms are masked in phase 3, so one code path serves all blocks.
//
// rtp dtype hedge: buffer may be int64 or int32. Read as 16 int32 words;
// little-endian int64 values < 4096 => all odd words zero => take even words.
__global__ __launch_bounds__(256, 2) void fused_kernel(const float* __restrict__ states,
                                                       const float* __restrict__ reasoning_mask,
                                                       const int* __restrict__ rtp_raw,
                                                       float* __restrict__ out) {
    extern __shared__ char smem[];
    float* s_part   = reinterpret_cast<float*>(smem + SM_SPART);   // [NDEL][64]
    float* delta_sm = reinterpret_cast<float*>(smem + SM_DELTA);   // [NDEL]

    const int b   = blockIdx.y;
    const int t0  = blockIdx.x * TC;
    const int tid = threadIdx.x;
    const int warp = tid >> 5;
    const int lane = tid & 31;
    const unsigned int nblocks = gridDim.x * gridDim.y;

    const float4* __restrict__ base =
        reinterpret_cast<const float4*>(states + (size_t)b * LL * (size_t)1024);

    // smem addresses for this thread's 16B slot in each ring row
    uint32_t ring_base = (uint32_t)__cvta_generic_to_shared(smem) + (uint32_t)(tid * 16);
    // slot s at ring_base + s*4096

    // ---- Phase 1 prologue: issue rows 0..RING-1 ----
    #pragma unroll
    for (int r = 0; r < RING; r++) {
        int row = t0 + r; if (row > LL - 1) row = LL - 1;
        cp_async16(ring_base + (uint32_t)(r * 4096), base + (size_t)row * 256 + tid);
        cp_commit();
    }
    cp_wait<RING - 1>();   // row 0 ready
    float4 prev = *reinterpret_cast<float4*>(smem + (size_t)(0 * 4096) + tid * 16);

    const int sp_col = warp * 8 + lane;   // valid when lane < 8

    // ---- main loop: deltas 0 .. NDEL-1; issue row i+RING while it exists ----
    // For i <= NROWS-1-RING (= 97): issue row i+RING, then wait_group RING-2
    //   -> rows <= i+2 complete, covering cur = row i+1.
    #pragma unroll 4
    for (int i = 0; i <= NROWS - 1 - RING; i++) {
        int row = t0 + i + RING; if (row > LL - 1) row = LL - 1;
        cp_async16(ring_base + (uint32_t)(((i + RING) & (RING - 1)) * 4096),
                   base + (size_t)row * 256 + tid);
        cp_commit();
        cp_wait<RING - 2>();   // rows <= i+2 done

        float4 cur = *reinterpret_cast<float4*>(
            smem + (size_t)(((i + 1) & (RING - 1)) * 4096) + tid * 16);
        float s = sqnorm_diff(cur, prev);
        s += __shfl_xor_sync(0xffffffffu, s, 16);
        s += __shfl_xor_sync(0xffffffffu, s, 8);
        if (lane < 8) s_part[i * 64 + sp_col] = s;
        prev = cur;
    }
    // ---- tail: all rows issued; wait for everything, then compute-only ----
    cp_wait<0>();
    #pragma unroll
    for (int i = NROWS - RING; i < NDEL; i++) {
        float4 cur = *reinterpret_cast<float4*>(
            smem + (size_t)(((i + 1) & (RING - 1)) * 4096) + tid * 16);
        float s = sqnorm_diff(cur, prev);
        s += __shfl_xor_sync(0xffffffffu, s, 16);
        s += __shfl_xor_sync(0xffffffffu, s, 8);
        if (lane < 8) s_part[i * 64 + sp_col] = s;
        prev = cur;
    }

    __syncthreads();

    // ---- Phase 2: reduce 64 partials per delta. Warp w handles deltas
    //      i = w, w+8, ... < NDEL (conflict-free LDS). ----
    for (int i = warp; i < NDEL; i += 8) {
        float v = s_part[i * 64 + lane] + s_part[i * 64 + lane + 32];
        #pragma unroll
        for (int o = 16; o > 0; o >>= 1)
            v += __shfl_xor_sync(0xffffffffu, v, o);
        if (lane == 0) delta_sm[i] = sqrtf(v);
    }

    __syncthreads();

    // ---- Phase 3: loss terms, warp 0 only (111 terms, 4 per lane) ----
    if (warp == 0) {
        int odd_or = 0;
        #pragma unroll
        for (int i = 1; i < 16; i += 2) odd_or |= rtp_raw[i];
        const int rtp_b = (odd_or == 0) ? rtp_raw[2 * b] : rtp_raw[b];

        float ws = 0.0f, ms = 0.0f;
        #pragma unroll
        for (int h = 0; h < 4; h++) {
            const int li = lane + 32 * h;     // local term index
            const int t = t0 + li;
            if (li < TC && t < NI) {
                float di = fmaxf(delta_sm[li + 1] - delta_sm[li], 0.0f);
                const float m = reasoning_mask[b * LL + t + 2];
                int dist = rtp_b - t - 2;
                if (dist < 0) dist = 0;
                const float w = (dist < 5) ? (2.0f + (float)(5 - dist) * 0.5f) : 1.0f;
                ws += di * m * w;
                ms += m;
            }
        }
        #pragma unroll
        for (int o = 16; o > 0; o >>= 1) {
            ws += __shfl_xor_sync(0xffffffffu, ws, o);
            ms += __shfl_xor_sync(0xffffffffu, ms, o);
        }
        if (lane == 0) {
            atomicAdd(&g_ws, ws);
            atomicAdd(&g_ms, ms);
            __threadfence();
            const unsigned int my = atomicAdd(&g_ticket, 1u);
            if (my == nblocks - 1u) {
                __threadfence();
                const float tws = *(volatile float*)&g_ws;
                const float tms = *(volatile float*)&g_ms;
                out[0] = tws / (tms + 1e-9f);
                // reset for next graph replay (all blocks done: safe)
                g_ws = 0.0f;
                g_ms = 0.0f;
                g_ticket = 0u;
            }
        }
    }
}

extern "C" void kernel_launch(void* const* d_in, const int* in_sizes, int n_in,
                              void* d_out, int out_size) {
    const float* states = (const float*)d_in[0];
    const float* rmask  = (const float*)d_in[1];
    const int*   rtp    = (const int*)d_in[2];
    float*       out    = (float*)d_out;

    cudaFuncSetAttribute(fused_kernel,
                         cudaFuncAttributeMaxDynamicSharedMemorySize, SM_TOTAL);

    dim3 grid(XBLK, BB);   // (37, 8) = 296 blocks = 148 SMs x 2
    fused_kernel<<<grid, 256, SM_TOTAL>>>(states, rmask, rtp, out);
}